// round 11
// baseline (speedup 1.0000x reference)
#include <cuda_runtime.h>
#include <math.h>
#include <stdint.h>

#define B_   2
#define L_   2048
#define DM   1024
#define DI   2048
#define DS   16
#define TOK  (B_*L_)
#define KCH  16            // split-K chunks for BC gemm
#define KCW  (DI / KCH)    // 128
#define CH   64            // scan time-chunk

// ---------------- scratch (device globals; no allocs allowed) ----------------
__device__ float g_xn[TOK * DM];
__device__ float g_xz[TOK * 2 * DI];
__device__ float g_xconv[TOK * DI];
__device__ float g_dt[TOK * DI];
__device__ float g_BC[TOK * 2 * DS];
__device__ float g_BCp[KCH][TOK * 2 * DS];   // split-K partials (8MB)
__device__ float g_y[TOK * DI];
__device__ float g_A[DI * DS];

// ---------------- helpers ----------------
__inline__ __device__ float warpsum(float v) {
    #pragma unroll
    for (int m = 16; m; m >>= 1) v += __shfl_xor_sync(0xffffffffu, v, m);
    return v;
}

#define RND_TF32(f) (__float_as_uint(f) + 0x1000u)   // round-to-nearest; mma ignores low 13 bits

__device__ __forceinline__ void mma_tf32(float* c, const uint32_t* a, const uint32_t* b) {
    asm volatile(
        "mma.sync.aligned.m16n8k8.row.col.f32.tf32.tf32.f32 "
        "{%0,%1,%2,%3}, {%4,%5,%6,%7}, {%8,%9}, {%0,%1,%2,%3};"
        : "+f"(c[0]), "+f"(c[1]), "+f"(c[2]), "+f"(c[3])
        : "r"(a[0]), "r"(a[1]), "r"(a[2]), "r"(a[3]), "r"(b[0]), "r"(b[1]));
}

#define LDSM4(r, addr) \
    asm volatile("ldmatrix.sync.aligned.m8n8.x4.shared.b16 {%0,%1,%2,%3}, [%4];" \
        : "=r"((r)[0]), "=r"((r)[1]), "=r"((r)[2]), "=r"((r)[3]) : "r"(addr))

// ======================================================================
//  mma.sync TF32 GEMM: C[M,N] = A[M,K] @ B[N,K]^T (+epilogue)
//  CTA 128x128, BK=16, 4 warps in 2x2, warp tile 64x64.
//  SMEM [m][20]: STS.128 stores; fragments via ldmatrix.x4 (conflict-free:
//  row stride 80B -> per-phase banks {20r mod 32} all distinct).
//  EPI: 0 none, 1 softplus(v+aux[col]), 2 v+aux[row*N+col]
// ======================================================================
template<int EPI>
__global__ void __launch_bounds__(128)
gemm_mma_kernel(const float* __restrict__ A, const float* __restrict__ Bw,
                float* __restrict__ C, int M, int N, int K,
                const float* __restrict__ aux)
{
    __shared__ __align__(16) float As[2][128][20];
    __shared__ __align__(16) float Bs[2][128][20];

    const int tid  = threadIdx.x;
    const int lane = tid & 31;
    const int warp = tid >> 5;
    const int g    = lane >> 2;
    const int tig  = lane & 3;
    const int wm   = warp >> 1;          // 0..1
    const int wn   = warp & 1;           // 0..1
    const int bm0  = blockIdx.y * 128;
    const int bn0  = blockIdx.x * 128;

    float acc[4][8][4];
    #pragma unroll
    for (int i = 0; i < 4; i++)
        #pragma unroll
        for (int j = 0; j < 8; j++)
            #pragma unroll
            for (int q = 0; q < 4; q++) acc[i][j][q] = 0.f;

    const int r0 = tid >> 2;   // 0..31 (+32e)
    const int kq = tid & 3;    // k-quad: owns k = 4kq..4kq+3

    // ldmatrix per-lane row addresses (bytes, shared space)
    const uint32_t aS = (uint32_t)__cvta_generic_to_shared(&As[0][0][0]);
    const uint32_t bS = (uint32_t)__cvta_generic_to_shared(&Bs[0][0][0]);
    // A tile i: lanes 0-7 rows m0..+7 k0, 8-15 rows +8 k0, 16-23 rows k0+4, 24-31 rows+8 k0+4
    const uint32_t aAddr = aS + (uint32_t)(((wm * 64 + (lane & 15)) * 20 + (lane >> 4) * 4) * 4);
    // B pair p: m0 rows n0..+7 k0 | m1 same rows k0+4 | m2 rows +8 k0 | m3 rows +8 k0+4
    const uint32_t bAddr = bS + (uint32_t)(((wn * 64 + (lane & 7) + ((lane >> 4) & 1) * 8) * 20
                                           + ((lane >> 3) & 1) * 4) * 4);
    const uint32_t BUFB = 128 * 20 * 4;   // 10240 bytes per buffer

    float4 ra[4], rb[4];

#define LDG_T(k0) do { \
    _Pragma("unroll") \
    for (int e = 0; e < 4; e++) { \
        ra[e] = *(const float4*)(A  + (size_t)(bm0 + r0 + 32*e) * K + (k0) + 4*kq); \
        rb[e] = *(const float4*)(Bw + (size_t)(bn0 + r0 + 32*e) * K + (k0) + 4*kq); \
    } } while (0)

#define STS_T(buf) do { \
    _Pragma("unroll") \
    for (int e = 0; e < 4; e++) { \
        uint4 u; \
        u = make_uint4(RND_TF32(ra[e].x), RND_TF32(ra[e].y), RND_TF32(ra[e].z), RND_TF32(ra[e].w)); \
        *(uint4*)&As[buf][r0 + 32*e][4*kq] = u; \
        u = make_uint4(RND_TF32(rb[e].x), RND_TF32(rb[e].y), RND_TF32(rb[e].z), RND_TF32(rb[e].w)); \
        *(uint4*)&Bs[buf][r0 + 32*e][4*kq] = u; \
    } } while (0)

    const int n_iter = K >> 4;
    LDG_T(0);
    STS_T(0);
    __syncthreads();

    for (int it = 0; it < n_iter; it++) {
        const uint32_t bufo = (uint32_t)(it & 1) * BUFB;
        if (it + 1 < n_iter) LDG_T((it + 1) << 4);

        #pragma unroll
        for (int ks = 0; ks < 2; ks++) {
            uint32_t af[4][4], bfp[4][4];
            #pragma unroll
            for (int i = 0; i < 4; i++)
                LDSM4(af[i], aAddr + bufo + (uint32_t)(i * 1280 + ks * 32));
            #pragma unroll
            for (int p = 0; p < 4; p++)
                LDSM4(bfp[p], bAddr + bufo + (uint32_t)(p * 1280 + ks * 32));
            #pragma unroll
            for (int i = 0; i < 4; i++)
                #pragma unroll
                for (int j = 0; j < 8; j++)
                    mma_tf32(acc[i][j], af[i], &bfp[j >> 1][(j & 1) * 2]);
        }
        // STS targets the buffer whose readers finished before the previous
        // barrier -> only ONE sync per iteration needed.
        if (it + 1 < n_iter) STS_T((it + 1) & 1);
        __syncthreads();
    }

    // ---- epilogue: direct STG (float2 pairs) ----
    #pragma unroll
    for (int i = 0; i < 4; i++) {
        const int row = bm0 + wm * 64 + i * 16 + g;
        #pragma unroll
        for (int j = 0; j < 8; j++) {
            const int col = bn0 + wn * 64 + j * 8 + 2 * tig;
            #pragma unroll
            for (int half = 0; half < 2; half++) {
                const int r = row + half * 8;
                float v0 = acc[i][j][half * 2 + 0];
                float v1 = acc[i][j][half * 2 + 1];
                size_t idx = (size_t)r * N + col;
                if (EPI == 1) {
                    v0 += aux[col];
                    v1 += aux[col + 1];
                    v0 = (v0 > 20.f) ? v0 : log1pf(__expf(v0));
                    v1 = (v1 > 20.f) ? v1 : log1pf(__expf(v1));
                } else if (EPI == 2) {
                    v0 += aux[idx];
                    v1 += aux[idx + 1];
                }
                *(float2*)(C + idx) = make_float2(v0, v1);
            }
        }
    }
#undef LDG_T
#undef STS_T
}

// ---------------- layernorm ----------------
__global__ void ln_kernel(const float* __restrict__ x, const float* __restrict__ w,
                          const float* __restrict__ b, float* __restrict__ out) {
    int t = blockIdx.x;
    int tid = threadIdx.x;
    const float* xr = x + (size_t)t * DM;
    float s = 0.f, sq = 0.f;
    for (int i = tid; i < DM; i += 256) { float v = xr[i]; s += v; sq += v * v; }
    s = warpsum(s); sq = warpsum(sq);
    __shared__ float sh0[8], sh1[8];
    int wi = tid >> 5, l = tid & 31;
    if (l == 0) { sh0[wi] = s; sh1[wi] = sq; }
    __syncthreads();
    if (wi == 0) {
        s  = (l < 8) ? sh0[l] : 0.f;
        sq = (l < 8) ? sh1[l] : 0.f;
        s = warpsum(s); sq = warpsum(sq);
        if (l == 0) { sh0[0] = s; sh1[0] = sq; }
    }
    __syncthreads();
    float mu  = sh0[0] * (1.f / DM);
    float var = sh1[0] * (1.f / DM) - mu * mu;
    float r = rsqrtf(var + 1e-5f);
    for (int i = tid; i < DM; i += 256)
        out[(size_t)t * DM + i] = (xr[i] - mu) * r * w[i] + b[i];
}

// ---------------- A = -exp(A_log) ----------------
__global__ void prep_A(const float* __restrict__ Al, float* __restrict__ A) {
    int i = blockIdx.x * blockDim.x + threadIdx.x;
    if (i < DI * DS) A[i] = -expf(Al[i]);
}

// ---------------- BC split-K partial: 32x32 tile over K-chunk of 128 ----------------
__global__ void __launch_bounds__(256) bc_partial_kernel(
    const float* __restrict__ A, const float* __restrict__ Bp, const float* __restrict__ Bp2)
{
    constexpr int BM = 32, BN = 32, BK = 16, TM = 2, TN = 2;
    constexpr int PAD = 4;
    __shared__ float As[BK][BM + PAD];
    __shared__ float Bs[BK][BN + PAD];
    int tid = threadIdx.x;
    int kc  = blockIdx.x;                // 0..15
    int bm0 = blockIdx.y * BM;
    int kbeg = kc * KCW;
    constexpr int TX = BN / TN;
    int tx = tid % TX;
    int ty = tid / TX;

    float acc[TM][TN] = {};
    constexpr int AF4 = BM * BK / 4;
    constexpr int BF4 = BN * BK / 4;
    constexpr int KQ  = BK / 4;

    for (int k0 = kbeg; k0 < kbeg + KCW; k0 += BK) {
        #pragma unroll
        for (int q = tid; q < AF4; q += 256) {
            int row = q / KQ, c = q % KQ;
            float4 f = *(const float4*)(A + (size_t)(bm0 + row) * DI + k0 + 4 * c);
            As[4*c+0][row] = f.x; As[4*c+1][row] = f.y;
            As[4*c+2][row] = f.z; As[4*c+3][row] = f.w;
        }
        #pragma unroll
        for (int q = tid; q < BF4; q += 256) {
            int row = q / KQ, c = q % KQ;
            const float* src = (row < 16) ? (Bp + (size_t)row * DI) : (Bp2 + (size_t)(row - 16) * DI);
            float4 f = *(const float4*)(src + k0 + 4 * c);
            Bs[4*c+0][row] = f.x; Bs[4*c+1][row] = f.y;
            Bs[4*c+2][row] = f.z; Bs[4*c+3][row] = f.w;
        }
        __syncthreads();
        #pragma unroll
        for (int k = 0; k < BK; k++) {
            float a[TM], b[TN];
            #pragma unroll
            for (int i = 0; i < TM; i++) a[i] = As[k][ty * TM + i];
            #pragma unroll
            for (int j = 0; j < TN; j++) b[j] = Bs[k][tx * TN + j];
            #pragma unroll
            for (int i = 0; i < TM; i++)
                #pragma unroll
                for (int j = 0; j < TN; j++)
                    acc[i][j] = fmaf(a[i], b[j], acc[i][j]);
        }
        __syncthreads();
    }
    #pragma unroll
    for (int i = 0; i < TM; i++)
        #pragma unroll
        for (int j = 0; j < TN; j++)
            g_BCp[kc][(size_t)(bm0 + ty * TM + i) * 32 + tx * TN + j] = acc[i][j];
}

__global__ void bc_reduce_kernel() {
    int idx = blockIdx.x * blockDim.x + threadIdx.x;
    if (idx >= TOK * 32) return;
    float s = 0.f;
    #pragma unroll
    for (int kc = 0; kc < KCH; kc++) s += g_BCp[kc][idx];
    g_BC[idx] = s;
}

// ---------------- causal depthwise conv (K=4) + SiLU ----------------
__global__ void conv_silu_kernel(const float* __restrict__ cw, const float* __restrict__ cb) {
    int idx = blockIdx.x * blockDim.x + threadIdx.x;
    if (idx >= TOK * DI) return;
    int token = idx / DI;
    int c = idx - token * DI;
    int b = token / L_;
    int t = token - b * L_;
    float sum = cb[c];
    #pragma unroll
    for (int k = 0; k < 4; k++) {
        int tt = t - 3 + k;
        if (tt >= 0)
            sum = fmaf(g_xz[((size_t)(b * L_ + tt)) * (2 * DI) + c], cw[c * 4 + k], sum);
    }
    float s = sum / (1.f + __expf(-sum));
    g_xconv[idx] = s;
}

// ======================================================================
//  selective scan, smem-staged & pipelined (CH=64: half the barriers)
// ======================================================================
__global__ void __launch_bounds__(512) scan_kernel(const float* __restrict__ Dv) {
    __shared__ float s_dt[2][CH][32];
    __shared__ float s_xc[2][CH][32];
    __shared__ float s_z [2][CH][32];
    __shared__ float s_bc[2][CH][32];
    __shared__ float s_y [CH][32];

    const int tid  = threadIdx.x;
    const int warp = tid >> 5;
    const int lane = tid & 31;
    const int b    = blockIdx.x >> 6;            // 64 d-blocks per batch
    const int dblk = (blockIdx.x & 63) * 32;
    const int n    = lane & 15;
    const int dl   = 2 * warp + (lane >> 4);
    const int d    = dblk + dl;

    const float a  = g_A[d * DS + n];
    const float Dd = Dv[d];
    const size_t tok0 = (size_t)b * L_;

    float r_dt[4], r_xc[4], r_z[4], r_bc[4];

#define SCAN_LDG(t0) do { \
    _Pragma("unroll") \
    for (int e = 0; e < 4; e++) { \
        size_t tok = tok0 + (t0) + warp + 16 * e; \
        r_dt[e] = g_dt   [tok * DI + dblk + lane]; \
        r_xc[e] = g_xconv[tok * DI + dblk + lane]; \
        r_z [e] = g_xz   [tok * 2 * DI + DI + dblk + lane]; \
        r_bc[e] = g_BC   [tok * 32 + lane]; \
    } } while (0)

#define SCAN_STS(buf) do { \
    _Pragma("unroll") \
    for (int e = 0; e < 4; e++) { \
        int i = warp + 16 * e; \
        s_dt[buf][i][lane] = r_dt[e]; \
        s_xc[buf][i][lane] = r_xc[e]; \
        s_z [buf][i][lane] = r_z [e]; \
        s_bc[buf][i][lane] = r_bc[e]; \
    } } while (0)

    SCAN_LDG(0);
    SCAN_STS(0);
    __syncthreads();

    float h = 0.f;
    const int n_chunks = L_ / CH;     // 32

    for (int c = 0; c < n_chunks; c++) {
        if (c + 1 < n_chunks) SCAN_LDG((c + 1) * CH);
        const int cur = c & 1;

        #pragma unroll
        for (int i = 0; i < CH; i++) {
            float dtv = s_dt[cur][i][dl];
            float xcv = s_xc[cur][i][dl];
            float Bv  = s_bc[cur][i][n];
            float Cv  = s_bc[cur][i][16 + n];
            float e = __expf(a * dtv);
            h = fmaf(h, e, xcv * dtv * Bv);
            float p = h * Cv;
            p += __shfl_xor_sync(0xffffffffu, p, 1);
            p += __shfl_xor_sync(0xffffffffu, p, 2);
            p += __shfl_xor_sync(0xffffffffu, p, 4);
            p += __shfl_xor_sync(0xffffffffu, p, 8);
            if (n == 0) {
                float zv = s_z[cur][i][dl];
                float sig = zv / (1.f + __expf(-zv));
                s_y[i][dl] = (p + xcv * Dd) * sig;
            }
        }
        __syncthreads();   // scan reads + s_y writes done

        #pragma unroll
        for (int e = 0; e < 4; e++) {
            int i = warp + 16 * e;
            g_y[(tok0 + c * CH + i) * DI + dblk + lane] = s_y[i][lane];
        }
        if (c + 1 < n_chunks) SCAN_STS((c + 1) & 1);
        __syncthreads();   // next buffer ready; s_y drained
    }
#undef SCAN_LDG
#undef SCAN_STS
}

// ---------------- launch ----------------
extern "C" void kernel_launch(void* const* d_in, const int* in_sizes, int n_in,
                              void* d_out, int out_size) {
    const float* x      = (const float*)d_in[0];
    const float* norm_w = (const float*)d_in[1];
    const float* norm_b = (const float*)d_in[2];
    const float* W_in   = (const float*)d_in[3];
    const float* conv_w = (const float*)d_in[4];
    const float* conv_b = (const float*)d_in[5];
    const float* W_dt   = (const float*)d_in[6];
    const float* b_dt   = (const float*)d_in[7];
    const float* W_B    = (const float*)d_in[8];
    const float* W_C    = (const float*)d_in[9];
    const float* Dv     = (const float*)d_in[10];
    const float* A_log  = (const float*)d_in[11];
    const float* W_out  = (const float*)d_in[12];
    float* out = (float*)d_out;

    float *p_xn, *p_xz, *p_xc, *p_dt, *p_y;
    cudaGetSymbolAddress((void**)&p_xn, g_xn);
    cudaGetSymbolAddress((void**)&p_xz, g_xz);
    cudaGetSymbolAddress((void**)&p_xc, g_xconv);
    cudaGetSymbolAddress((void**)&p_dt, g_dt);
    cudaGetSymbolAddress((void**)&p_y,  g_y);

    // 1. layernorm
    ln_kernel<<<TOK, 256>>>(x, norm_w, norm_b, p_xn);

    // 2. in-proj: xz = xn @ W_in^T    [4096 x 4096 x 1024]
    {
        dim3 grid((2 * DI) / 128, TOK / 128);
        gemm_mma_kernel<0><<<grid, 128>>>(p_xn, W_in, p_xz, TOK, 2 * DI, DM, nullptr);
    }

    // 3. conv + silu
    conv_silu_kernel<<<(TOK * DI) / 256, 256>>>(conv_w, conv_b);

    // 4a. dt = softplus(x_conv @ W_dt^T + b_dt)   [4096 x 2048 x 2048]
    {
        dim3 grid(DI / 128, TOK / 128);
        gemm_mma_kernel<1><<<grid, 128>>>(p_xc, W_dt, p_dt, TOK, DI, DI, b_dt);
    }

    // 4b. [B|C] split-K partials + reduce
    {
        dim3 grid(KCH, TOK / 32);
        bc_partial_kernel<<<grid, 256>>>(p_xc, W_B, W_C);
        bc_reduce_kernel<<<(TOK * 32 + 255) / 256, 256>>>();
    }

    // 4c. A = -exp(A_log)
    {
        float* p_A; cudaGetSymbolAddress((void**)&p_A, g_A);
        prep_A<<<(DI * DS + 255) / 256, 256>>>(A_log, p_A);
    }

    // 5. selective scan + gating (smem-staged pipeline)
    scan_kernel<<<B_ * (DI / 32), 512>>>(Dv);

    // 6. out = residual + y @ W_out^T   [4096 x 1024 x 2048]
    {
        dim3 grid(DM / 128, TOK / 128);
        gemm_mma_kernel<2><<<grid, 128>>>(p_y, W_out, out, TOK, DM, DI, x);
    }
}

// round 12
// speedup vs baseline: 1.6215x; 1.6215x over previous
#include <cuda_runtime.h>
#include <math.h>
#include <stdint.h>

#define B_   2
#define L_   2048
#define DM   1024
#define DI   2048
#define DS   16
#define TOK  (B_*L_)
#define KCH  16            // split-K chunks for BC gemm
#define KCW  (DI / KCH)    // 128
#define CH   32            // scan time-chunk

// ---------------- scratch (device globals; no allocs allowed) ----------------
__device__ float g_xn[TOK * DM];
__device__ float g_xz[TOK * 2 * DI];
__device__ float g_xconv[TOK * DI];
__device__ float g_dt[TOK * DI];
__device__ float g_BC[TOK * 2 * DS];
__device__ float g_BCp[KCH][TOK * 2 * DS];   // split-K partials (8MB)
__device__ float g_y[TOK * DI];
__device__ float g_A[DI * DS];

// ---------------- helpers ----------------
__inline__ __device__ float warpsum(float v) {
    #pragma unroll
    for (int m = 16; m; m >>= 1) v += __shfl_xor_sync(0xffffffffu, v, m);
    return v;
}

#define RND_TF32(f) (__float_as_uint(f) + 0x1000u)   // round-to-nearest; mma ignores low 13 bits

__device__ __forceinline__ void mma_tf32(float* c, const uint32_t* a, const uint32_t* b) {
    asm volatile(
        "mma.sync.aligned.m16n8k8.row.col.f32.tf32.tf32.f32 "
        "{%0,%1,%2,%3}, {%4,%5,%6,%7}, {%8,%9}, {%0,%1,%2,%3};"
        : "+f"(c[0]), "+f"(c[1]), "+f"(c[2]), "+f"(c[3])
        : "r"(a[0]), "r"(a[1]), "r"(a[2]), "r"(a[3]), "r"(b[0]), "r"(b[1]));
}

// ======================================================================
//  mma.sync TF32 GEMM (R10 winner, verbatim): C = A[M,K] @ B[N,K]^T
//  CTA 128x128, BK=16, 4 warps in 2x2, warp tile 64x64.
//  SMEM [m][k+4]: STS.128 stores, conflict-free frag LDS, 1 sync/iter.
//  EPI: 0 none, 1 softplus(v+aux[col]), 2 v+aux[row*N+col]
// ======================================================================
template<int EPI>
__global__ void __launch_bounds__(128)
gemm_mma_kernel(const float* __restrict__ A, const float* __restrict__ Bw,
                float* __restrict__ C, int M, int N, int K,
                const float* __restrict__ aux)
{
    __shared__ float As[2][128][20];
    __shared__ float Bs[2][128][20];

    const int tid  = threadIdx.x;
    const int lane = tid & 31;
    const int warp = tid >> 5;
    const int g    = lane >> 2;
    const int tig  = lane & 3;
    const int wm   = warp >> 1;          // 0..1
    const int wn   = warp & 1;           // 0..1
    const int bm0  = blockIdx.y * 128;
    const int bn0  = blockIdx.x * 128;

    float acc[4][8][4];
    #pragma unroll
    for (int i = 0; i < 4; i++)
        #pragma unroll
        for (int j = 0; j < 8; j++)
            #pragma unroll
            for (int q = 0; q < 4; q++) acc[i][j][q] = 0.f;

    const int r0 = tid >> 2;   // 0..31 (+32e)
    const int kq = tid & 3;    // k-quad: owns k = 4kq..4kq+3

    float4 ra[4], rb[4];

#define LDG_T(k0) do { \
    _Pragma("unroll") \
    for (int e = 0; e < 4; e++) { \
        ra[e] = *(const float4*)(A  + (size_t)(bm0 + r0 + 32*e) * K + (k0) + 4*kq); \
        rb[e] = *(const float4*)(Bw + (size_t)(bn0 + r0 + 32*e) * K + (k0) + 4*kq); \
    } } while (0)

#define STS_T(buf) do { \
    _Pragma("unroll") \
    for (int e = 0; e < 4; e++) { \
        uint4 u; \
        u = make_uint4(RND_TF32(ra[e].x), RND_TF32(ra[e].y), RND_TF32(ra[e].z), RND_TF32(ra[e].w)); \
        *(uint4*)&As[buf][r0 + 32*e][4*kq] = u; \
        u = make_uint4(RND_TF32(rb[e].x), RND_TF32(rb[e].y), RND_TF32(rb[e].z), RND_TF32(rb[e].w)); \
        *(uint4*)&Bs[buf][r0 + 32*e][4*kq] = u; \
    } } while (0)

    const int n_iter = K >> 4;
    LDG_T(0);
    STS_T(0);
    __syncthreads();

    for (int it = 0; it < n_iter; it++) {
        const int cur = it & 1;
        if (it + 1 < n_iter) LDG_T((it + 1) << 4);

        #pragma unroll
        for (int ks = 0; ks < 2; ks++) {
            uint32_t af[4][4], bf[8][2];
            const int k0 = ks * 8 + tig;
            const int k1 = k0 + 4;
            #pragma unroll
            for (int i = 0; i < 4; i++) {
                const int row = wm * 64 + i * 16 + g;
                af[i][0] = __float_as_uint(As[cur][row][k0]);
                af[i][1] = __float_as_uint(As[cur][row + 8][k0]);
                af[i][2] = __float_as_uint(As[cur][row][k1]);
                af[i][3] = __float_as_uint(As[cur][row + 8][k1]);
            }
            #pragma unroll
            for (int j = 0; j < 8; j++) {
                const int col = wn * 64 + j * 8 + g;
                bf[j][0] = __float_as_uint(Bs[cur][col][k0]);
                bf[j][1] = __float_as_uint(Bs[cur][col][k1]);
            }
            #pragma unroll
            for (int i = 0; i < 4; i++)
                #pragma unroll
                for (int j = 0; j < 8; j++)
                    mma_tf32(acc[i][j], af[i], bf[j]);
        }
        // STS targets the buffer whose readers finished before the previous
        // barrier -> only ONE sync per iteration needed.
        if (it + 1 < n_iter) STS_T((it + 1) & 1);
        __syncthreads();
    }

    // ---- epilogue: direct STG (float2 pairs) ----
    #pragma unroll
    for (int i = 0; i < 4; i++) {
        const int row = bm0 + wm * 64 + i * 16 + g;
        #pragma unroll
        for (int j = 0; j < 8; j++) {
            const int col = bn0 + wn * 64 + j * 8 + 2 * tig;
            #pragma unroll
            for (int half = 0; half < 2; half++) {
                const int r = row + half * 8;
                float v0 = acc[i][j][half * 2 + 0];
                float v1 = acc[i][j][half * 2 + 1];
                size_t idx = (size_t)r * N + col;
                if (EPI == 1) {
                    v0 += aux[col];
                    v1 += aux[col + 1];
                    v0 = (v0 > 20.f) ? v0 : log1pf(__expf(v0));
                    v1 = (v1 > 20.f) ? v1 : log1pf(__expf(v1));
                } else if (EPI == 2) {
                    v0 += aux[idx];
                    v1 += aux[idx + 1];
                }
                *(float2*)(C + idx) = make_float2(v0, v1);
            }
        }
    }
#undef LDG_T
#undef STS_T
}

// ---------------- layernorm ----------------
__global__ void ln_kernel(const float* __restrict__ x, const float* __restrict__ w,
                          const float* __restrict__ b, float* __restrict__ out) {
    int t = blockIdx.x;
    int tid = threadIdx.x;
    const float* xr = x + (size_t)t * DM;
    float s = 0.f, sq = 0.f;
    for (int i = tid; i < DM; i += 256) { float v = xr[i]; s += v; sq += v * v; }
    s = warpsum(s); sq = warpsum(sq);
    __shared__ float sh0[8], sh1[8];
    int wi = tid >> 5, l = tid & 31;
    if (l == 0) { sh0[wi] = s; sh1[wi] = sq; }
    __syncthreads();
    if (wi == 0) {
        s  = (l < 8) ? sh0[l] : 0.f;
        sq = (l < 8) ? sh1[l] : 0.f;
        s = warpsum(s); sq = warpsum(sq);
        if (l == 0) { sh0[0] = s; sh1[0] = sq; }
    }
    __syncthreads();
    float mu  = sh0[0] * (1.f / DM);
    float var = sh1[0] * (1.f / DM) - mu * mu;
    float r = rsqrtf(var + 1e-5f);
    for (int i = tid; i < DM; i += 256)
        out[(size_t)t * DM + i] = (xr[i] - mu) * r * w[i] + b[i];
}

// ---------------- A = -exp(A_log) ----------------
__global__ void prep_A(const float* __restrict__ Al, float* __restrict__ A) {
    int i = blockIdx.x * blockDim.x + threadIdx.x;
    if (i < DI * DS) A[i] = -expf(Al[i]);
}

// ---------------- BC split-K partial: 32x32 tile over K-chunk of 128 ----------------
__global__ void __launch_bounds__(256) bc_partial_kernel(
    const float* __restrict__ A, const float* __restrict__ Bp, const float* __restrict__ Bp2)
{
    constexpr int BM = 32, BN = 32, BK = 16, TM = 2, TN = 2;
    constexpr int PAD = 4;
    __shared__ float As[BK][BM + PAD];
    __shared__ float Bs[BK][BN + PAD];
    int tid = threadIdx.x;
    int kc  = blockIdx.x;                // 0..15
    int bm0 = blockIdx.y * BM;
    int kbeg = kc * KCW;
    constexpr int TX = BN / TN;
    int tx = tid % TX;
    int ty = tid / TX;

    float acc[TM][TN] = {};
    constexpr int AF4 = BM * BK / 4;
    constexpr int BF4 = BN * BK / 4;
    constexpr int KQ  = BK / 4;

    for (int k0 = kbeg; k0 < kbeg + KCW; k0 += BK) {
        #pragma unroll
        for (int q = tid; q < AF4; q += 256) {
            int row = q / KQ, c = q % KQ;
            float4 f = *(const float4*)(A + (size_t)(bm0 + row) * DI + k0 + 4 * c);
            As[4*c+0][row] = f.x; As[4*c+1][row] = f.y;
            As[4*c+2][row] = f.z; As[4*c+3][row] = f.w;
        }
        #pragma unroll
        for (int q = tid; q < BF4; q += 256) {
            int row = q / KQ, c = q % KQ;
            const float* src = (row < 16) ? (Bp + (size_t)row * DI) : (Bp2 + (size_t)(row - 16) * DI);
            float4 f = *(const float4*)(src + k0 + 4 * c);
            Bs[4*c+0][row] = f.x; Bs[4*c+1][row] = f.y;
            Bs[4*c+2][row] = f.z; Bs[4*c+3][row] = f.w;
        }
        __syncthreads();
        #pragma unroll
        for (int k = 0; k < BK; k++) {
            float a[TM], b[TN];
            #pragma unroll
            for (int i = 0; i < TM; i++) a[i] = As[k][ty * TM + i];
            #pragma unroll
            for (int j = 0; j < TN; j++) b[j] = Bs[k][tx * TN + j];
            #pragma unroll
            for (int i = 0; i < TM; i++)
                #pragma unroll
                for (int j = 0; j < TN; j++)
                    acc[i][j] = fmaf(a[i], b[j], acc[i][j]);
        }
        __syncthreads();
    }
    #pragma unroll
    for (int i = 0; i < TM; i++)
        #pragma unroll
        for (int j = 0; j < TN; j++)
            g_BCp[kc][(size_t)(bm0 + ty * TM + i) * 32 + tx * TN + j] = acc[i][j];
}

__global__ void bc_reduce_kernel() {
    int idx = blockIdx.x * blockDim.x + threadIdx.x;
    if (idx >= TOK * 32) return;
    float s = 0.f;
    #pragma unroll
    for (int kc = 0; kc < KCH; kc++) s += g_BCp[kc][idx];
    g_BC[idx] = s;
}

// ---------------- causal depthwise conv (K=4) + SiLU ----------------
__global__ void conv_silu_kernel(const float* __restrict__ cw, const float* __restrict__ cb) {
    int idx = blockIdx.x * blockDim.x + threadIdx.x;
    if (idx >= TOK * DI) return;
    int token = idx / DI;
    int c = idx - token * DI;
    int b = token / L_;
    int t = token - b * L_;
    float sum = cb[c];
    #pragma unroll
    for (int k = 0; k < 4; k++) {
        int tt = t - 3 + k;
        if (tt >= 0)
            sum = fmaf(g_xz[((size_t)(b * L_ + tt)) * (2 * DI) + c], cw[c * 4 + k], sum);
    }
    float s = sum / (1.f + __expf(-sum));
    g_xconv[idx] = s;
}

// ======================================================================
//  selective scan v2: 8 lanes per channel, 2 states/lane, 3-shfl reduce.
//  Block = 256 thr = 8 warps handles (batch b, 32 d-channels);
//  warp w owns dl = 4w..4w+3; lane: dgrp = lane>>3, sub = lane&7;
//  states n = sub and n = sub+8.  Time in 64 chunks of CH=32, double-buffered.
// ======================================================================
__global__ void __launch_bounds__(256) scan_kernel(const float* __restrict__ Dv) {
    __shared__ float s_dt[2][CH][32];
    __shared__ float s_xc[2][CH][32];
    __shared__ float s_z [2][CH][32];
    __shared__ float s_bc[2][CH][32];
    __shared__ float s_y [CH][32];

    const int tid  = threadIdx.x;
    const int warp = tid >> 5;           // 0..7
    const int lane = tid & 31;
    const int b    = blockIdx.x >> 6;    // 64 d-blocks per batch
    const int dblk = (blockIdx.x & 63) * 32;
    const int sub  = lane & 7;           // state base index
    const int dgrp = lane >> 3;          // 0..3
    const int dl   = 4 * warp + dgrp;    // local channel 0..31
    const int d    = dblk + dl;

    const float a0 = g_A[d * DS + sub];
    const float a1 = g_A[d * DS + sub + 8];
    const float Dd = Dv[d];
    const size_t tok0 = (size_t)b * L_;

    float r_dt[4], r_xc[4], r_z[4], r_bc[4];

#define SCAN_LDG(t0) do { \
    _Pragma("unroll") \
    for (int e = 0; e < 4; e++) { \
        size_t tok = tok0 + (t0) + warp + 8 * e; \
        r_dt[e] = g_dt   [tok * DI + dblk + lane]; \
        r_xc[e] = g_xconv[tok * DI + dblk + lane]; \
        r_z [e] = g_xz   [tok * 2 * DI + DI + dblk + lane]; \
        r_bc[e] = g_BC   [tok * 32 + lane]; \
    } } while (0)

#define SCAN_STS(buf) do { \
    _Pragma("unroll") \
    for (int e = 0; e < 4; e++) { \
        int i = warp + 8 * e; \
        s_dt[buf][i][lane] = r_dt[e]; \
        s_xc[buf][i][lane] = r_xc[e]; \
        s_z [buf][i][lane] = r_z [e]; \
        s_bc[buf][i][lane] = r_bc[e]; \
    } } while (0)

    SCAN_LDG(0);
    SCAN_STS(0);
    __syncthreads();

    float h0 = 0.f, h1 = 0.f;
    const int n_chunks = L_ / CH;     // 64

    for (int c = 0; c < n_chunks; c++) {
        if (c + 1 < n_chunks) SCAN_LDG((c + 1) * CH);
        const int cur = c & 1;

        #pragma unroll
        for (int i = 0; i < CH; i++) {
            float dtv = s_dt[cur][i][dl];
            float xcv = s_xc[cur][i][dl];
            float B0  = s_bc[cur][i][sub];
            float B8  = s_bc[cur][i][sub + 8];
            float C0  = s_bc[cur][i][16 + sub];
            float C8  = s_bc[cur][i][24 + sub];
            float e0 = __expf(a0 * dtv);
            float e1 = __expf(a1 * dtv);
            float w  = xcv * dtv;
            h0 = fmaf(h0, e0, w * B0);
            h1 = fmaf(h1, e1, w * B8);
            float p = fmaf(h1, C8, h0 * C0);
            p += __shfl_xor_sync(0xffffffffu, p, 1);
            p += __shfl_xor_sync(0xffffffffu, p, 2);
            p += __shfl_xor_sync(0xffffffffu, p, 4);
            if (sub == 0) {
                float zv = s_z[cur][i][dl];
                float sig = zv / (1.f + __expf(-zv));
                s_y[i][dl] = (p + xcv * Dd) * sig;
            }
        }
        __syncthreads();   // scan reads + s_y writes done

        #pragma unroll
        for (int e = 0; e < 4; e++) {
            int i = warp + 8 * e;
            g_y[(tok0 + c * CH + i) * DI + dblk + lane] = s_y[i][lane];
        }
        if (c + 1 < n_chunks) SCAN_STS((c + 1) & 1);
        __syncthreads();   // next buffer ready; s_y drained
    }
#undef SCAN_LDG
#undef SCAN_STS
}

// ---------------- launch ----------------
extern "C" void kernel_launch(void* const* d_in, const int* in_sizes, int n_in,
                              void* d_out, int out_size) {
    const float* x      = (const float*)d_in[0];
    const float* norm_w = (const float*)d_in[1];
    const float* norm_b = (const float*)d_in[2];
    const float* W_in   = (const float*)d_in[3];
    const float* conv_w = (const float*)d_in[4];
    const float* conv_b = (const float*)d_in[5];
    const float* W_dt   = (const float*)d_in[6];
    const float* b_dt   = (const float*)d_in[7];
    const float* W_B    = (const float*)d_in[8];
    const float* W_C    = (const float*)d_in[9];
    const float* Dv     = (const float*)d_in[10];
    const float* A_log  = (const float*)d_in[11];
    const float* W_out  = (const float*)d_in[12];
    float* out = (float*)d_out;

    float *p_xn, *p_xz, *p_xc, *p_dt, *p_y;
    cudaGetSymbolAddress((void**)&p_xn, g_xn);
    cudaGetSymbolAddress((void**)&p_xz, g_xz);
    cudaGetSymbolAddress((void**)&p_xc, g_xconv);
    cudaGetSymbolAddress((void**)&p_dt, g_dt);
    cudaGetSymbolAddress((void**)&p_y,  g_y);

    // 1. layernorm
    ln_kernel<<<TOK, 256>>>(x, norm_w, norm_b, p_xn);

    // 2. in-proj: xz = xn @ W_in^T    [4096 x 4096 x 1024]
    {
        dim3 grid((2 * DI) / 128, TOK / 128);
        gemm_mma_kernel<0><<<grid, 128>>>(p_xn, W_in, p_xz, TOK, 2 * DI, DM, nullptr);
    }

    // 3. conv + silu
    conv_silu_kernel<<<(TOK * DI) / 256, 256>>>(conv_w, conv_b);

    // 4a. dt = softplus(x_conv @ W_dt^T + b_dt)   [4096 x 2048 x 2048]
    {
        dim3 grid(DI / 128, TOK / 128);
        gemm_mma_kernel<1><<<grid, 128>>>(p_xc, W_dt, p_dt, TOK, DI, DI, b_dt);
    }

    // 4b. [B|C] split-K partials + reduce
    {
        dim3 grid(KCH, TOK / 32);
        bc_partial_kernel<<<grid, 256>>>(p_xc, W_B, W_C);
        bc_reduce_kernel<<<(TOK * 32 + 255) / 256, 256>>>();
    }

    // 4c. A = -exp(A_log)
    {
        float* p_A; cudaGetSymbolAddress((void**)&p_A, g_A);
        prep_A<<<(DI * DS + 255) / 256, 256>>>(A_log, p_A);
    }

    // 5. selective scan + gating (8-lane groups, 3-shfl reduce)
    scan_kernel<<<B_ * (DI / 32), 256>>>(Dv);

    // 6. out = residual + y @ W_out^T   [4096 x 1024 x 2048]
    {
        dim3 grid(DM / 128, TOK / 128);
        gemm_mma_kernel<2><<<grid, 128>>>(p_y, W_out, out, TOK, DM, DI, x);
    }
}

// round 13
// speedup vs baseline: 1.6664x; 1.0277x over previous
#include <cuda_runtime.h>
#include <math.h>
#include <stdint.h>

#define B_   2
#define L_   2048
#define DM   1024
#define DI   2048
#define DS   16
#define TOK  (B_*L_)
#define KCH  16            // split-K chunks for BC gemm
#define KCW  (DI / KCH)    // 128
#define CH   32            // scan time-chunk

// ---------------- scratch (device globals; no allocs allowed) ----------------
__device__ float g_xn[TOK * DM];
__device__ float g_xz[TOK * 2 * DI];
__device__ float g_xconv[TOK * DI];
__device__ float g_dt[TOK * DI];
__device__ float g_BC[TOK * 2 * DS];
__device__ float g_BCp[KCH][TOK * 2 * DS];   // split-K partials (8MB)
__device__ float g_y[TOK * DI];
__device__ float g_A[DI * DS];
__device__ float g_Win[2 * DI * DM];         // pre-rounded weights (tf32-rna)
__device__ float g_Wdt[DI * DI];
__device__ float g_Wout[DM * DI];

// ---------------- helpers ----------------
__inline__ __device__ float warpsum(float v) {
    #pragma unroll
    for (int m = 16; m; m >>= 1) v += __shfl_xor_sync(0xffffffffu, v, m);
    return v;
}

#define RND_TF32(f) (__float_as_uint(f) + 0x1000u)   // round-to-nearest; mma ignores low 13 bits
#define RNDF(f) __uint_as_float(RND_TF32(f))

__device__ __forceinline__ void mma_tf32(float* c, const uint32_t* a, const uint32_t* b) {
    asm volatile(
        "mma.sync.aligned.m16n8k8.row.col.f32.tf32.tf32.f32 "
        "{%0,%1,%2,%3}, {%4,%5,%6,%7}, {%8,%9}, {%0,%1,%2,%3};"
        : "+f"(c[0]), "+f"(c[1]), "+f"(c[2]), "+f"(c[3])
        : "r"(a[0]), "r"(a[1]), "r"(a[2]), "r"(a[3]), "r"(b[0]), "r"(b[1]));
}

// ---------------- tf32 round-copy (weights prep) ----------------
__global__ void rnd_copy(const float* __restrict__ src, float* __restrict__ dst, int n4) {
    int i = blockIdx.x * blockDim.x + threadIdx.x;
    if (i < n4) {
        float4 f = ((const float4*)src)[i];
        uint4 u = make_uint4(RND_TF32(f.x), RND_TF32(f.y), RND_TF32(f.z), RND_TF32(f.w));
        ((uint4*)dst)[i] = u;
    }
}

// ======================================================================
//  mma.sync TF32 GEMM: C = A[M,K] @ B[N,K]^T  (A,B pre-rounded to tf32)
//  CTA 128x128, BK=16, 4 warps in 2x2, warp tile 64x64.
//  SMEM [m][k+4]; loads via cp.async (overlapped with MMA), frag LDS
//  conflict-free.  EPI: 0 none, 1 softplus(v+aux[col]), 2 v+aux[idx]
// ======================================================================
template<int EPI>
__global__ void __launch_bounds__(128)
gemm_mma_kernel(const float* __restrict__ A, const float* __restrict__ Bw,
                float* __restrict__ C, int M, int N, int K,
                const float* __restrict__ aux)
{
    __shared__ __align__(16) float As[2][128][20];
    __shared__ __align__(16) float Bs[2][128][20];

    const int tid  = threadIdx.x;
    const int lane = tid & 31;
    const int warp = tid >> 5;
    const int g    = lane >> 2;
    const int tig  = lane & 3;
    const int wm   = warp >> 1;          // 0..1
    const int wn   = warp & 1;           // 0..1
    const int bm0  = blockIdx.y * 128;
    const int bn0  = blockIdx.x * 128;

    float acc[4][8][4];
    #pragma unroll
    for (int i = 0; i < 4; i++)
        #pragma unroll
        for (int j = 0; j < 8; j++)
            #pragma unroll
            for (int q = 0; q < 4; q++) acc[i][j][q] = 0.f;

    const int r0 = tid >> 2;   // 0..31 (+32e)
    const int kq = tid & 3;    // k-quad: owns k = 4kq..4kq+3

    const uint32_t aSm = (uint32_t)__cvta_generic_to_shared(&As[0][0][0])
                       + (uint32_t)(r0 * 80 + kq * 16);
    const uint32_t bSm = (uint32_t)__cvta_generic_to_shared(&Bs[0][0][0])
                       + (uint32_t)(r0 * 80 + kq * 16);
    const uint32_t BUFB = 128 * 20 * 4;   // 10240 B per buffer

#define CPA_T(buf, k0) do { \
    const uint32_t bo = (uint32_t)(buf) * BUFB; \
    _Pragma("unroll") \
    for (int e = 0; e < 4; e++) { \
        asm volatile("cp.async.ca.shared.global [%0], [%1], 16;" :: \
            "r"(aSm + bo + (uint32_t)(e * 2560)), \
            "l"(A + (size_t)(bm0 + r0 + 32*e) * K + (k0) + 4*kq)); \
        asm volatile("cp.async.ca.shared.global [%0], [%1], 16;" :: \
            "r"(bSm + bo + (uint32_t)(e * 2560)), \
            "l"(Bw + (size_t)(bn0 + r0 + 32*e) * K + (k0) + 4*kq)); \
    } \
    asm volatile("cp.async.commit_group;"); \
} while (0)

    const int n_iter = K >> 4;
    CPA_T(0, 0);
    asm volatile("cp.async.wait_group 0;");
    __syncthreads();

    for (int it = 0; it < n_iter; it++) {
        const int cur = it & 1;
        if (it + 1 < n_iter) CPA_T((it + 1) & 1, (it + 1) << 4);

        #pragma unroll
        for (int ks = 0; ks < 2; ks++) {
            uint32_t af[4][4], bf[8][2];
            const int k0 = ks * 8 + tig;
            const int k1 = k0 + 4;
            #pragma unroll
            for (int i = 0; i < 4; i++) {
                const int row = wm * 64 + i * 16 + g;
                af[i][0] = __float_as_uint(As[cur][row][k0]);
                af[i][1] = __float_as_uint(As[cur][row + 8][k0]);
                af[i][2] = __float_as_uint(As[cur][row][k1]);
                af[i][3] = __float_as_uint(As[cur][row + 8][k1]);
            }
            #pragma unroll
            for (int j = 0; j < 8; j++) {
                const int col = wn * 64 + j * 8 + g;
                bf[j][0] = __float_as_uint(Bs[cur][col][k0]);
                bf[j][1] = __float_as_uint(Bs[cur][col][k1]);
            }
            #pragma unroll
            for (int i = 0; i < 4; i++)
                #pragma unroll
                for (int j = 0; j < 8; j++)
                    mma_tf32(acc[i][j], af[i], bf[j]);
        }
        if (it + 1 < n_iter) asm volatile("cp.async.wait_group 0;");
        __syncthreads();
    }

    // ---- epilogue: direct STG (float2 pairs) ----
    #pragma unroll
    for (int i = 0; i < 4; i++) {
        const int row = bm0 + wm * 64 + i * 16 + g;
        #pragma unroll
        for (int j = 0; j < 8; j++) {
            const int col = bn0 + wn * 64 + j * 8 + 2 * tig;
            #pragma unroll
            for (int half = 0; half < 2; half++) {
                const int r = row + half * 8;
                float v0 = acc[i][j][half * 2 + 0];
                float v1 = acc[i][j][half * 2 + 1];
                size_t idx = (size_t)r * N + col;
                if (EPI == 1) {
                    v0 += aux[col];
                    v1 += aux[col + 1];
                    v0 = (v0 > 20.f) ? v0 : log1pf(__expf(v0));
                    v1 = (v1 > 20.f) ? v1 : log1pf(__expf(v1));
                } else if (EPI == 2) {
                    v0 += aux[idx];
                    v1 += aux[idx + 1];
                }
                *(float2*)(C + idx) = make_float2(v0, v1);
            }
        }
    }
#undef CPA_T
}

// ---------------- layernorm (writes tf32-rounded output) ----------------
__global__ void ln_kernel(const float* __restrict__ x, const float* __restrict__ w,
                          const float* __restrict__ b, float* __restrict__ out) {
    int t = blockIdx.x;
    int tid = threadIdx.x;
    const float* xr = x + (size_t)t * DM;
    float s = 0.f, sq = 0.f;
    for (int i = tid; i < DM; i += 256) { float v = xr[i]; s += v; sq += v * v; }
    s = warpsum(s); sq = warpsum(sq);
    __shared__ float sh0[8], sh1[8];
    int wi = tid >> 5, l = tid & 31;
    if (l == 0) { sh0[wi] = s; sh1[wi] = sq; }
    __syncthreads();
    if (wi == 0) {
        s  = (l < 8) ? sh0[l] : 0.f;
        sq = (l < 8) ? sh1[l] : 0.f;
        s = warpsum(s); sq = warpsum(sq);
        if (l == 0) { sh0[0] = s; sh1[0] = sq; }
    }
    __syncthreads();
    float mu  = sh0[0] * (1.f / DM);
    float var = sh1[0] * (1.f / DM) - mu * mu;
    float r = rsqrtf(var + 1e-5f);
    for (int i = tid; i < DM; i += 256)
        out[(size_t)t * DM + i] = RNDF((xr[i] - mu) * r * w[i] + b[i]);
}

// ---------------- A = -exp(A_log) ----------------
__global__ void prep_A(const float* __restrict__ Al, float* __restrict__ A) {
    int i = blockIdx.x * blockDim.x + threadIdx.x;
    if (i < DI * DS) A[i] = -expf(Al[i]);
}

// ---------------- BC split-K partial: 32x32 tile over K-chunk of 128 ----------------
__global__ void __launch_bounds__(256) bc_partial_kernel(
    const float* __restrict__ A, const float* __restrict__ Bp, const float* __restrict__ Bp2)
{
    constexpr int BM = 32, BN = 32, BK = 16, TM = 2, TN = 2;
    constexpr int PAD = 4;
    __shared__ float As[BK][BM + PAD];
    __shared__ float Bs[BK][BN + PAD];
    int tid = threadIdx.x;
    int kc  = blockIdx.x;                // 0..15
    int bm0 = blockIdx.y * BM;
    int kbeg = kc * KCW;
    constexpr int TX = BN / TN;
    int tx = tid % TX;
    int ty = tid / TX;

    float acc[TM][TN] = {};
    constexpr int AF4 = BM * BK / 4;
    constexpr int BF4 = BN * BK / 4;
    constexpr int KQ  = BK / 4;

    for (int k0 = kbeg; k0 < kbeg + KCW; k0 += BK) {
        #pragma unroll
        for (int q = tid; q < AF4; q += 256) {
            int row = q / KQ, c = q % KQ;
            float4 f = *(const float4*)(A + (size_t)(bm0 + row) * DI + k0 + 4 * c);
            As[4*c+0][row] = f.x; As[4*c+1][row] = f.y;
            As[4*c+2][row] = f.z; As[4*c+3][row] = f.w;
        }
        #pragma unroll
        for (int q = tid; q < BF4; q += 256) {
            int row = q / KQ, c = q % KQ;
            const float* src = (row < 16) ? (Bp + (size_t)row * DI) : (Bp2 + (size_t)(row - 16) * DI);
            float4 f = *(const float4*)(src + k0 + 4 * c);
            Bs[4*c+0][row] = f.x; Bs[4*c+1][row] = f.y;
            Bs[4*c+2][row] = f.z; Bs[4*c+3][row] = f.w;
        }
        __syncthreads();
        #pragma unroll
        for (int k = 0; k < BK; k++) {
            float a[TM], b[TN];
            #pragma unroll
            for (int i = 0; i < TM; i++) a[i] = As[k][ty * TM + i];
            #pragma unroll
            for (int j = 0; j < TN; j++) b[j] = Bs[k][tx * TN + j];
            #pragma unroll
            for (int i = 0; i < TM; i++)
                #pragma unroll
                for (int j = 0; j < TN; j++)
                    acc[i][j] = fmaf(a[i], b[j], acc[i][j]);
        }
        __syncthreads();
    }
    #pragma unroll
    for (int i = 0; i < TM; i++)
        #pragma unroll
        for (int j = 0; j < TN; j++)
            g_BCp[kc][(size_t)(bm0 + ty * TM + i) * 32 + tx * TN + j] = acc[i][j];
}

__global__ void bc_reduce_kernel() {
    int idx = blockIdx.x * blockDim.x + threadIdx.x;
    if (idx >= TOK * 32) return;
    float s = 0.f;
    #pragma unroll
    for (int kc = 0; kc < KCH; kc++) s += g_BCp[kc][idx];
    g_BC[idx] = s;
}

// ---------------- causal depthwise conv (K=4) + SiLU (tf32-rounded out) ----------------
__global__ void conv_silu_kernel(const float* __restrict__ cw, const float* __restrict__ cb) {
    int idx = blockIdx.x * blockDim.x + threadIdx.x;
    if (idx >= TOK * DI) return;
    int token = idx / DI;
    int c = idx - token * DI;
    int b = token / L_;
    int t = token - b * L_;
    float sum = cb[c];
    #pragma unroll
    for (int k = 0; k < 4; k++) {
        int tt = t - 3 + k;
        if (tt >= 0)
            sum = fmaf(g_xz[((size_t)(b * L_ + tt)) * (2 * DI) + c], cw[c * 4 + k], sum);
    }
    float s = sum / (1.f + __expf(-sum));
    g_xconv[idx] = RNDF(s);
}

// ======================================================================
//  selective scan v2 (R12 winner): 8 lanes/channel, 2 states/lane,
//  3-shfl reduce; writes tf32-rounded y for the out-GEMM.
// ======================================================================
__global__ void __launch_bounds__(256) scan_kernel(const float* __restrict__ Dv) {
    __shared__ float s_dt[2][CH][32];
    __shared__ float s_xc[2][CH][32];
    __shared__ float s_z [2][CH][32];
    __shared__ float s_bc[2][CH][32];
    __shared__ float s_y [CH][32];

    const int tid  = threadIdx.x;
    const int warp = tid >> 5;           // 0..7
    const int lane = tid & 31;
    const int b    = blockIdx.x >> 6;    // 64 d-blocks per batch
    const int dblk = (blockIdx.x & 63) * 32;
    const int sub  = lane & 7;           // state base index
    const int dgrp = lane >> 3;          // 0..3
    const int dl   = 4 * warp + dgrp;    // local channel 0..31
    const int d    = dblk + dl;

    const float a0 = g_A[d * DS + sub];
    const float a1 = g_A[d * DS + sub + 8];
    const float Dd = Dv[d];
    const size_t tok0 = (size_t)b * L_;

    float r_dt[4], r_xc[4], r_z[4], r_bc[4];

#define SCAN_LDG(t0) do { \
    _Pragma("unroll") \
    for (int e = 0; e < 4; e++) { \
        size_t tok = tok0 + (t0) + warp + 8 * e; \
        r_dt[e] = g_dt   [tok * DI + dblk + lane]; \
        r_xc[e] = g_xconv[tok * DI + dblk + lane]; \
        r_z [e] = g_xz   [tok * 2 * DI + DI + dblk + lane]; \
        r_bc[e] = g_BC   [tok * 32 + lane]; \
    } } while (0)

#define SCAN_STS(buf) do { \
    _Pragma("unroll") \
    for (int e = 0; e < 4; e++) { \
        int i = warp + 8 * e; \
        s_dt[buf][i][lane] = r_dt[e]; \
        s_xc[buf][i][lane] = r_xc[e]; \
        s_z [buf][i][lane] = r_z [e]; \
        s_bc[buf][i][lane] = r_bc[e]; \
    } } while (0)

    SCAN_LDG(0);
    SCAN_STS(0);
    __syncthreads();

    float h0 = 0.f, h1 = 0.f;
    const int n_chunks = L_ / CH;     // 64

    for (int c = 0; c < n_chunks; c++) {
        if (c + 1 < n_chunks) SCAN_LDG((c + 1) * CH);
        const int cur = c & 1;

        #pragma unroll
        for (int i = 0; i < CH; i++) {
            float dtv = s_dt[cur][i][dl];
            float xcv = s_xc[cur][i][dl];
            float B0  = s_bc[cur][i][sub];
            float B8  = s_bc[cur][i][sub + 8];
            float C0  = s_bc[cur][i][16 + sub];
            float C8  = s_bc[cur][i][24 + sub];
            float e0 = __expf(a0 * dtv);
            float e1 = __expf(a1 * dtv);
            float w  = xcv * dtv;
            h0 = fmaf(h0, e0, w * B0);
            h1 = fmaf(h1, e1, w * B8);
            float p = fmaf(h1, C8, h0 * C0);
            p += __shfl_xor_sync(0xffffffffu, p, 1);
            p += __shfl_xor_sync(0xffffffffu, p, 2);
            p += __shfl_xor_sync(0xffffffffu, p, 4);
            if (sub == 0) {
                float zv = s_z[cur][i][dl];
                float sig = zv / (1.f + __expf(-zv));
                s_y[i][dl] = (p + xcv * Dd) * sig;
            }
        }
        __syncthreads();   // scan reads + s_y writes done

        #pragma unroll
        for (int e = 0; e < 4; e++) {
            int i = warp + 8 * e;
            g_y[(tok0 + c * CH + i) * DI + dblk + lane] = RNDF(s_y[i][lane]);
        }
        if (c + 1 < n_chunks) SCAN_STS((c + 1) & 1);
        __syncthreads();   // next buffer ready; s_y drained
    }
#undef SCAN_LDG
#undef SCAN_STS
}

// ---------------- launch ----------------
extern "C" void kernel_launch(void* const* d_in, const int* in_sizes, int n_in,
                              void* d_out, int out_size) {
    const float* x      = (const float*)d_in[0];
    const float* norm_w = (const float*)d_in[1];
    const float* norm_b = (const float*)d_in[2];
    const float* W_in   = (const float*)d_in[3];
    const float* conv_w = (const float*)d_in[4];
    const float* conv_b = (const float*)d_in[5];
    const float* W_dt   = (const float*)d_in[6];
    const float* b_dt   = (const float*)d_in[7];
    const float* W_B    = (const float*)d_in[8];
    const float* W_C    = (const float*)d_in[9];
    const float* Dv     = (const float*)d_in[10];
    const float* A_log  = (const float*)d_in[11];
    const float* W_out  = (const float*)d_in[12];
    float* out = (float*)d_out;

    float *p_xn, *p_xz, *p_xc, *p_dt, *p_y, *p_Win, *p_Wdt, *p_Wout;
    cudaGetSymbolAddress((void**)&p_xn, g_xn);
    cudaGetSymbolAddress((void**)&p_xz, g_xz);
    cudaGetSymbolAddress((void**)&p_xc, g_xconv);
    cudaGetSymbolAddress((void**)&p_dt, g_dt);
    cudaGetSymbolAddress((void**)&p_y,  g_y);
    cudaGetSymbolAddress((void**)&p_Win,  g_Win);
    cudaGetSymbolAddress((void**)&p_Wdt,  g_Wdt);
    cudaGetSymbolAddress((void**)&p_Wout, g_Wout);

    // 0. weights -> tf32-rounded copies (overlappable with ln)
    rnd_copy<<<(2 * DI * DM / 4 + 255) / 256, 256>>>(W_in,  p_Win,  2 * DI * DM / 4);
    rnd_copy<<<(DI * DI / 4 + 255) / 256, 256>>>(W_dt,  p_Wdt,  DI * DI / 4);
    rnd_copy<<<(DM * DI / 4 + 255) / 256, 256>>>(W_out, p_Wout, DM * DI / 4);

    // 1. layernorm (rounded out)
    ln_kernel<<<TOK, 256>>>(x, norm_w, norm_b, p_xn);

    // 2. in-proj: xz = xn @ W_in^T    [4096 x 4096 x 1024]
    {
        dim3 grid((2 * DI) / 128, TOK / 128);
        gemm_mma_kernel<0><<<grid, 128>>>(p_xn, p_Win, p_xz, TOK, 2 * DI, DM, nullptr);
    }

    // 3. conv + silu (rounded out)
    conv_silu_kernel<<<(TOK * DI) / 256, 256>>>(conv_w, conv_b);

    // 4a. dt = softplus(x_conv @ W_dt^T + b_dt)   [4096 x 2048 x 2048]
    {
        dim3 grid(DI / 128, TOK / 128);
        gemm_mma_kernel<1><<<grid, 128>>>(p_xc, p_Wdt, p_dt, TOK, DI, DI, b_dt);
    }

    // 4b. [B|C] split-K partials + reduce
    {
        dim3 grid(KCH, TOK / 32);
        bc_partial_kernel<<<grid, 256>>>(p_xc, W_B, W_C);
        bc_reduce_kernel<<<(TOK * 32 + 255) / 256, 256>>>();
    }

    // 4c. A = -exp(A_log)
    {
        float* p_A; cudaGetSymbolAddress((void**)&p_A, g_A);
        prep_A<<<(DI * DS + 255) / 256, 256>>>(A_log, p_A);
    }

    // 5. selective scan + gating (rounded y out)
    scan_kernel<<<B_ * (DI / 32), 256>>>(Dv);

    // 6. out = residual + y @ W_out^T   [4096 x 1024 x 2048]
    {
        dim3 grid(DM / 128, TOK / 128);
        gemm_mma_kernel<2><<<grid, 128>>>(p_y, p_Wout, out, TOK, DM, DI, x);
    }
}